// round 15
// baseline (speedup 1.0000x reference)
#include <cuda_runtime.h>
#include <cstdint>

#define BSZ 128
#define NN 48
#define NP1 49
#define DM 32
#define DMODEL 128
#define NHEAD 4
#define HD 32
#define TOTALE (BSZ*NN*NHEAD*NP1)

typedef unsigned long long ull;

// ---------------- device scratch ----------------
__device__ float g_P[BSZ * NP1 * DMODEL];
__device__ float g_Q[BSZ * NN * DMODEL];
__device__ float g_Wg[DMODEL * 384];
__device__ float g_M2[DM * 384];
__device__ float g_S[384];
__device__ float g_C[384];
__device__ float g_PQ2[(size_t)12416 * 384];

// ---------------- helpers ----------------
__device__ __forceinline__ float warp_sum(float v) {
    #pragma unroll
    for (int o = 16; o > 0; o >>= 1) v += __shfl_xor_sync(0xffffffffu, v, o);
    return v;
}
__device__ __forceinline__ float warp_max(float v) {
    #pragma unroll
    for (int o = 16; o > 0; o >>= 1) v = fmaxf(v, __shfl_xor_sync(0xffffffffu, v, o));
    return v;
}
__device__ __forceinline__ unsigned rotl32(unsigned v, int r) { return (v << r) | (v >> (32 - r)); }
__device__ __forceinline__ ull fma2(ull a, ull b, ull c) {
    ull d; asm("fma.rn.f32x2 %0, %1, %2, %3;" : "=l"(d) : "l"(a), "l"(b), "l"(c)); return d;
}
__device__ __forceinline__ ull add2(ull a, ull b) {
    ull d; asm("add.rn.f32x2 %0, %1, %2;" : "=l"(d) : "l"(a), "l"(b)); return d;
}
__device__ __forceinline__ ull pack2(float lo, float hi) {
    ull d; asm("mov.b64 %0, {%1, %2};" : "=l"(d) : "f"(lo), "f"(hi)); return d;
}
__device__ __forceinline__ ull dup2(float v) {
    ull d; asm("mov.b64 %0, {%1, %1};" : "=l"(d) : "f"(v)); return d;
}
__device__ __forceinline__ void unpack2(ull v, float& lo, float& hi) {
    asm("mov.b64 {%0, %1}, %2;" : "=f"(lo), "=f"(hi) : "l"(v));
}
__device__ float gumbel_noise(unsigned idx) {   // JAX partitionable threefry (verified R2-R12)
    unsigned x0 = 0u, x1 = idx;
    const unsigned ks0 = 0u, ks1 = 42u, ks2 = 0x1BD11BDAu ^ 0u ^ 42u;
    x0 += ks0; x1 += ks1;
#define TFR(r) { x0 += x1; x1 = rotl32(x1, r); x1 ^= x0; }
    TFR(13) TFR(15) TFR(26) TFR(6)   x0 += ks1; x1 += ks2 + 1u;
    TFR(17) TFR(29) TFR(16) TFR(24)  x0 += ks2; x1 += ks0 + 2u;
    TFR(13) TFR(15) TFR(26) TFR(6)   x0 += ks0; x1 += ks1 + 3u;
    TFR(17) TFR(29) TFR(16) TFR(24)  x0 += ks1; x1 += ks2 + 4u;
    TFR(13) TFR(15) TFR(26) TFR(6)   x0 += ks2; x1 += ks0 + 5u;
#undef TFR
    unsigned bits = x0 ^ x1;
    float u = __uint_as_float((bits >> 9) | 0x3f800000u) - 1.0f;
    return -logf(-log1pf(-u));
}

// ---------------- k0: build Wg, S, C, M2 (unchanged) ----------------
__global__ void k0_fold(const float* __restrict__ W_qkv, const float* __restrict__ b_qkv,
                        const float* __restrict__ W1, const float* __restrict__ b1,
                        const float* __restrict__ ln_g, const float* __restrict__ ln_b,
                        const float* __restrict__ W_embed) {
    int n = blockIdx.x, d = threadIdx.x;
    const float scale = 0.1767766952966369f;
    int h = (n - 256) >> 5, dp = (n - 256) & 31;
    float wf;
    if (n < 128) wf = W_qkv[d * 384 + n] * scale;
    else if (n < 256) wf = W_qkv[d * 384 + n];
    else {
        float acc = 0.f;
        #pragma unroll 8
        for (int c = 0; c < 32; c++)
            acc = fmaf(W_qkv[d * 384 + 256 + 32 * h + c], W1[c * 32 + dp], acc);
        wf = acc;
    }
    float wg = ln_g[d] * wf;
    g_Wg[d * 384 + n] = wg;
    __shared__ float sw[128], red[128];
    sw[d] = wg;
    red[d] = wg;
    __syncthreads();
    for (int s = 64; s > 0; s >>= 1) { if (d < s) red[d] += red[d + s]; __syncthreads(); }
    float Sv = red[0];
    __syncthreads();
    red[d] = ln_b[d] * wf;
    __syncthreads();
    for (int s = 64; s > 0; s >>= 1) { if (d < s) red[d] += red[d + s]; __syncthreads(); }
    if (d == 0) {
        float bias;
        if (n < 128) bias = b_qkv[n] * scale;
        else if (n < 256) bias = b_qkv[n];
        else {
            bias = b1[dp];
            #pragma unroll 8
            for (int c = 0; c < 32; c++)
                bias = fmaf(b_qkv[256 + 32 * h + c], W1[c * 32 + dp], bias);
        }
        g_S[n] = Sv;
        g_C[n] = red[0] + bias;
    }
    if (d < 32) {
        float acc = 0.f;
        #pragma unroll 16
        for (int dd = 0; dd < 128; dd++)
            acc = fmaf(W_embed[(64 + d) * 128 + dd], sw[dd], acc);
        g_M2[d * 384 + n] = acc;
    }
}

// ---------------- k1: P, Q (unchanged) ----------------
__global__ void k1_pq(const float* __restrict__ x, const float* __restrict__ attn_mask,
                      const float* __restrict__ W_embed, const float* __restrict__ b_embed) {
    int b = blockIdx.x / NP1, n = blockIdx.x % NP1, d = threadIdx.x;
    if (n == NN) { g_P[((size_t)b * NP1 + NN) * DMODEL + d] = b_embed[d]; return; }
    __shared__ float am[NN];
    __shared__ float xm[DM];
    if (d < NN) am[d] = attn_mask[((size_t)b * NN + n) * NN + d];
    __syncthreads();
    float s = 0.f;
    #pragma unroll
    for (int c = 0; c < NN; c++) s += am[c];
    if (d < DM) xm[d] = x[((size_t)b * NN + n) * DM + d] * ((s > 0.f) ? 1.f : 0.f);
    __syncthreads();
    float p = b_embed[d], q = 0.f;
    #pragma unroll
    for (int c = 0; c < DM; c++) {
        float xc = xm[c];
        p = fmaf(xc, W_embed[c * DMODEL + d], p);
        q = fmaf(xc, W_embed[(DM + c) * DMODEL + d], q);
    }
    g_P[((size_t)b * NP1 + n) * DMODEL + d] = p;
    g_Q[((size_t)b * NN + n) * DMODEL + d] = q;
}

// ---------------- kP: PQ2 = [P;Q] @ Wg (unchanged) ----------------
__global__ void __launch_bounds__(256) kP_gemm() {
    __shared__ float wt[16 * 384];
    int tid = threadIdx.x, lane = tid & 31, w = tid >> 5;
    int base = blockIdx.x * 56;
    ull acc2[7][6];
    #pragma unroll
    for (int rr = 0; rr < 7; rr++)
        #pragma unroll
        for (int k = 0; k < 6; k++) acc2[rr][k] = 0ull;
    for (int d0 = 0; d0 < DMODEL; d0 += 16) {
        for (int t = tid; t < 16 * 384 / 4; t += 256)
            ((float4*)wt)[t] = ((const float4*)(g_Wg + (size_t)d0 * 384))[t];
        __syncthreads();
        float eReg[7];
        #pragma unroll
        for (int rr = 0; rr < 7; rr++) {
            int gr = base + w + 8 * rr;
            float v = 0.f;
            if (gr < 12416 && (lane < 16)) {
                v = (gr < 6272) ? g_P[(size_t)gr * DMODEL + d0 + lane]
                                : g_Q[(size_t)(gr - 6272) * DMODEL + d0 + lane];
            }
            eReg[rr] = v;
        }
        #pragma unroll 4
        for (int dd = 0; dd < 16; dd++) {
            ulonglong2 wv0 = ((const ulonglong2*)(wt + dd * 384))[lane];
            ulonglong2 wv1 = ((const ulonglong2*)(wt + dd * 384 + 128))[lane];
            ulonglong2 wv2 = ((const ulonglong2*)(wt + dd * 384 + 256))[lane];
            #pragma unroll
            for (int rr = 0; rr < 7; rr++) {
                ull e2 = dup2(__shfl_sync(0xffffffffu, eReg[rr], dd));
                acc2[rr][0] = fma2(e2, wv0.x, acc2[rr][0]);
                acc2[rr][1] = fma2(e2, wv0.y, acc2[rr][1]);
                acc2[rr][2] = fma2(e2, wv1.x, acc2[rr][2]);
                acc2[rr][3] = fma2(e2, wv1.y, acc2[rr][3]);
                acc2[rr][4] = fma2(e2, wv2.x, acc2[rr][4]);
                acc2[rr][5] = fma2(e2, wv2.y, acc2[rr][5]);
            }
        }
        __syncthreads();
    }
    #pragma unroll
    for (int rr = 0; rr < 7; rr++) {
        int gr = base + w + 8 * rr;
        if (gr < 12416) {
            #pragma unroll
            for (int k4 = 0; k4 < 3; k4++) {
                float v0, v1, v2, v3;
                unpack2(acc2[rr][2*k4], v0, v1);
                unpack2(acc2[rr][2*k4+1], v2, v3);
                *(float4*)(g_PQ2 + (size_t)gr * 384 + 128 * k4 + 4 * lane) = make_float4(v0, v1, v2, v3);
            }
        }
    }
}

// ---------------- k3 smem layout (floats) — 12 warps, 5-row groups ----------------
#define NT      384
#define NWARP   12
#define OFF_AE  0        /* 60*32 = 1920 */
#define OFF_BIG 1920
#define QSTR    132
#define OFF_Q   1920
#define OFF_V   8388
#define KTSTR   52
#define OFF_KT  14856
#define OFF_M   21512
#define OFF_S   21576
#define OFF_C   21960
#define OFF_W2  22344
#define OFF_G   22376
#define OFF_G2  22576
#define SMEM3_FLOATS 22772
#define SMEM3_BYTES (SMEM3_FLOATS * 4)

__global__ void __launch_bounds__(NT, 2) k3_attn(
    const float* __restrict__ A, const float* __restrict__ attn_mask,
    const float* __restrict__ W_embed, const float* __restrict__ W2,
    const float* __restrict__ b2, float* __restrict__ out) {
    extern __shared__ float sm[];
    int bj = blockIdx.x, b = bj / NN, j = bj % NN;
    int tid = threadIdx.x, lane = tid & 31, w = tid >> 5;
    bool wzero = (w == 0);
    float* sAE = sm + OFF_AE;
    float* sWA = sm + OFF_BIG;
    float* sM2 = sm + OFF_BIG;
    float* sQ  = sm + OFF_Q;
    float* sV  = sm + OFF_V;
    float* sKT = sm + OFF_KT;
    float* sM  = sm + OFF_M;
    float* sS  = sm + OFF_S;
    float* sC  = sm + OFF_C;
    float* sW2 = sm + OFF_W2;
    float* sG  = sm + OFF_G;
    float* sG2 = sm + OFF_G2;

    // ---- init loads (+ precompute gumbel noise) ----
    if (tid < 64) sM[tid] = (tid < NN) ? attn_mask[((size_t)b * NN + j) * NN + tid]
                                       : (tid == NN ? 1.0f : 0.0f);
    if (tid < 32) sW2[tid] = W2[tid];
    for (int t = tid; t < 384; t += NT) { sS[t] = g_S[t]; sC[t] = g_C[t]; }   // FIX: strided, full coverage
    for (int t = tid; t < DM * DMODEL; t += NT) sWA[t] = W_embed[(2 * DM) * DMODEL + t];
    for (int t = tid; t < 128 * 3; t += NT) sKT[(t / 3) * KTSTR + 49 + (t % 3)] = 0.f;
    if (tid < 196) sG2[tid] = gumbel_noise((unsigned)bj * 196u + (unsigned)tid);
    __syncthreads();

    // ---- stage masked A rows (rows w, w+12, ..., 48 for w==0) ----
    #pragma unroll
    for (int rr = 0; rr < 5; rr++) {
        int row = w + NWARP * rr;
        if (rr < 4 || wzero) {
            float a = 0.f;
            if (row < NN) a = A[(((size_t)b * NN + row) * NN + j) * DM + lane] * sM[row];
            sAE[(w * 5 + rr) * DM + lane] = a;
        }
    }
    __syncwarp();

    // ---- LN stats: raw = P + Q + a@WA ----
    float rsR[5], msR[5];
    {
        const float2* Pb2 = (const float2*)(g_P + (size_t)b * NP1 * DMODEL);
        const float2* Qb2 = (const float2*)(g_Q + ((size_t)b * NN + j) * DMODEL);
        const ull* wt2 = (const ull*)sWA;
        float2 qva = Qb2[lane], qvb = Qb2[32 + lane];
        ull e0[5], e1[5];
        #pragma unroll
        for (int rr = 0; rr < 5; rr++) {
            int row = w + NWARP * rr;
            if (rr < 4 || wzero) {
                float2 p0 = Pb2[row * 64 + lane], p1 = Pb2[row * 64 + 32 + lane];
                e0[rr] = pack2(p0.x + qva.x, p0.y + qva.y);
                e1[rr] = pack2(p1.x + qvb.x, p1.y + qvb.y);
            }
        }
        #pragma unroll 2
        for (int cg = 0; cg < 8; cg++) {
            float4 a4[5];
            #pragma unroll
            for (int rr = 0; rr < 5; rr++)
                if (rr < 4 || wzero) a4[rr] = *(const float4*)(sAE + (w * 5 + rr) * DM + 4 * cg);
            #pragma unroll
            for (int t = 0; t < 4; t++) {
                int c = 4 * cg + t;
                ull wv0 = wt2[c * 64 + lane], wv1 = wt2[c * 64 + 32 + lane];
                #pragma unroll
                for (int rr = 0; rr < 5; rr++) {
                    if (rr < 4 || wzero) {
                        ull ac = dup2(((const float*)&a4[rr])[t]);
                        e0[rr] = fma2(ac, wv0, e0[rr]);
                        e1[rr] = fma2(ac, wv1, e1[rr]);
                    }
                }
            }
        }
        #pragma unroll
        for (int rr = 0; rr < 5; rr++) {
            if (rr < 4 || wzero) {
                float v0, v1, v2, v3;
                unpack2(e0[rr], v0, v1); unpack2(e1[rr], v2, v3);
                float mu = warp_sum(v0 + v1 + v2 + v3) * (1.0f / DMODEL);
                float d0 = v0 - mu, d1 = v1 - mu, d2 = v2 - mu, d3 = v3 - mu;
                float rs = rsqrtf(warp_sum(d0*d0 + d1*d1 + d2*d2 + d3*d3) * (1.0f / DMODEL) + 1e-5f);
                rsR[rr] = rs;
                msR[rr] = rs * mu;
            }
        }
    }
    __syncthreads();

    // ---- load M2 tile (overwrites sWA region) ----
    for (int t = tid; t < DM * 384 / 4; t += NT)
        ((float4*)sM2)[t] = ((const float4*)g_M2)[t];
    __syncthreads();

    // ---- qkv: acc = P2 + Q2 + a@M2 ----
    ull acc2[5][6];
    {
        const ull* q2p = (const ull*)(g_PQ2 + (size_t)(6272 + b * NN + j) * 384);
        ull q2u[6];
        #pragma unroll
        for (int k4 = 0; k4 < 3; k4++) {
            q2u[2*k4]   = q2p[64 * k4 + 2 * lane];
            q2u[2*k4+1] = q2p[64 * k4 + 2 * lane + 1];
        }
        #pragma unroll
        for (int rr = 0; rr < 5; rr++) {
            int row = w + NWARP * rr;
            if (rr < 4 || wzero) {
                const float4* p2r = (const float4*)(g_PQ2 + (size_t)(b * NP1 + row) * 384);
                #pragma unroll
                for (int k4 = 0; k4 < 3; k4++) {
                    float4 p4 = p2r[32 * k4 + lane];
                    acc2[rr][2*k4]   = add2(pack2(p4.x, p4.y), q2u[2*k4]);
                    acc2[rr][2*k4+1] = add2(pack2(p4.z, p4.w), q2u[2*k4+1]);
                }
            }
        }
        #pragma unroll 2
        for (int cg = 0; cg < 8; cg++) {
            float4 a4[5];
            #pragma unroll
            for (int rr = 0; rr < 5; rr++)
                if (rr < 4 || wzero) a4[rr] = *(const float4*)(sAE + (w * 5 + rr) * DM + 4 * cg);
            #pragma unroll
            for (int t = 0; t < 4; t++) {
                int c = 4 * cg + t;
                ulonglong2 wv0 = ((const ulonglong2*)(sM2 + c * 384))[lane];
                ulonglong2 wv1 = ((const ulonglong2*)(sM2 + c * 384 + 128))[lane];
                ulonglong2 wv2 = ((const ulonglong2*)(sM2 + c * 384 + 256))[lane];
                #pragma unroll
                for (int rr = 0; rr < 5; rr++) {
                    if (rr < 4 || wzero) {
                        ull ac = dup2(((const float*)&a4[rr])[t]);
                        acc2[rr][0] = fma2(ac, wv0.x, acc2[rr][0]);
                        acc2[rr][1] = fma2(ac, wv0.y, acc2[rr][1]);
                        acc2[rr][2] = fma2(ac, wv1.x, acc2[rr][2]);
                        acc2[rr][3] = fma2(ac, wv1.y, acc2[rr][3]);
                        acc2[rr][4] = fma2(ac, wv2.x, acc2[rr][4]);
                        acc2[rr][5] = fma2(ac, wv2.y, acc2[rr][5]);
                    }
                }
            }
        }
    }
    __syncthreads();

    // ---- epilogue + scatter q / k^T / v' ----
    const ull* sS2 = (const ull*)sS;
    const ull* sC2 = (const ull*)sC;
    #pragma unroll
    for (int rr = 0; rr < 5; rr++) {
        int row = w + NWARP * rr;
        if (rr < 4 || wzero) {
            ull rs2 = dup2(rsR[rr]), nm2 = dup2(-msR[rr]);
            float o[12];
            #pragma unroll
            for (int k4 = 0; k4 < 3; k4++) {
                #pragma unroll
                for (int u = 0; u < 2; u++) {
                    int k = 2 * k4 + u;
                    ull sv = sS2[64 * k4 + 2 * lane + u];
                    ull cv = sC2[64 * k4 + 2 * lane + u];
                    ull res = fma2(rs2, acc2[rr][k], fma2(nm2, sv, cv));
                    unpack2(res, o[4*k4 + 2*u], o[4*k4 + 2*u + 1]);
                }
            }
            *(float4*)(sQ + row * QSTR + 4 * lane) = make_float4(o[0], o[1], o[2], o[3]);
            *(float4*)(sV + row * QSTR + 4 * lane) = make_float4(o[8], o[9], o[10], o[11]);
            int kd = 4 * lane;
            sKT[kd * KTSTR + row] = o[4];
            sKT[(kd + 1) * KTSTR + row] = o[5];
            sKT[(kd + 2) * KTSTR + row] = o[6];
            sKT[(kd + 3) * KTSTR + row] = o[7];
        }
    }
    __syncthreads();

    // ---- attention: blk = (head h, 7 i-rows), strided over 12 warps ----
    float b2v = b2[0], w2r = sW2[lane];
    float m0 = sM[2 * lane], m1 = sM[2 * lane + 1];
    bool vj0 = (2 * lane) < NP1, vj1 = (2 * lane + 1) < NP1;
    for (int blk = w; blk < 28; blk += NWARP) {
        int h = blk & 3, ibase = (blk >> 2) * 7;
        ull s2[7];
        #pragma unroll
        for (int r = 0; r < 7; r++) s2[r] = 0ull;
        const float* ktb = sKT + (h * HD) * KTSTR + 2 * lane;
        #pragma unroll 2
        for (int dq = 0; dq < 8; dq++) {
            float4 q4[7];
            #pragma unroll
            for (int r = 0; r < 7; r++)
                q4[r] = *(const float4*)(sQ + (ibase + r) * QSTR + h * HD + 4 * dq);
            #pragma unroll
            for (int t = 0; t < 4; t++) {
                int d = 4 * dq + t;
                ull kv2 = (lane < 26) ? *(const ull*)(ktb + d * KTSTR) : 0ull;
                #pragma unroll
                for (int r = 0; r < 7; r++) {
                    ull qd = dup2(((const float*)&q4[r])[t]);
                    s2[r] = fma2(qd, kv2, s2[r]);
                }
            }
        }
        ull p2[7];
        #pragma unroll
        for (int r = 0; r < 7; r++) {
            float mi = sM[ibase + r];
            float s0, s1;
            unpack2(s2[r], s0, s1);
            s0 = vj0 ? ((mi * m0 > 0.f) ? s0 : -1e9f) : -INFINITY;
            s1 = vj1 ? ((mi * m1 > 0.f) ? s1 : -1e9f) : -INFINITY;
            float mx = warp_max(fmaxf(s0, s1));
            float e0 = vj0 ? __expf(s0 - mx) : 0.f;
            float e1 = vj1 ? __expf(s1 - mx) : 0.f;
            float inv = 1.0f / warp_sum(e0 + e1);
            p2[r] = pack2(e0 * inv, e1 * inv);
        }
        ull t2[7];
        #pragma unroll
        for (int r = 0; r < 7; r++) t2[r] = 0ull;
        const float* vb = sV + h * HD + lane;
        #pragma unroll 5
        for (int jp = 0; jp < 25; jp++) {
            ull v2 = pack2(vb[(2 * jp) * QSTR], vb[(2 * jp + 1) * QSTR]);
            #pragma unroll
            for (int r = 0; r < 7; r++) {
                ull pp = __shfl_sync(0xffffffffu, p2[r], jp);
                t2[r] = fma2(pp, v2, t2[r]);
            }
        }
        #pragma unroll
        for (int r = 0; r < 7; r++) {
            float tlo, thi;
            unpack2(t2[r], tlo, thi);
            float t = fmaxf(tlo + thi, 0.f);
            float gp = warp_sum(t * w2r);
            if (lane == 0) sG[h * NP1 + ibase + r] = gp + b2v;
        }
    }
    __syncthreads();

    // ---- em softmax + gumbel (warp = head; noise precomputed) ----
    if (w < NHEAD) {
        int h = w, i0 = lane, i1 = lane + 32;
        bool has1 = (i1 < NP1);
        float g0 = sG[h * NP1 + i0];
        float g1 = has1 ? sG[h * NP1 + i1] : -INFINITY;
        float mx = warp_max(fmaxf(g0, g1));
        float e0 = __expf(g0 - mx), e1 = has1 ? __expf(g1 - mx) : 0.f;
        float inv = 1.0f / warp_sum(e0 + e1);
        float em0 = e0 * inv * sM[i0];
        float em1 = has1 ? e1 * inv * sM[i1] : 0.f;
        float den = warp_sum(em0 + em1) + 1e-10f;
        em0 /= den; em1 /= den;
        size_t base = (((size_t)b * NN + j) * NHEAD + h) * NP1;
        out[base + i0] = em0;
        if (has1) out[base + i1] = em1;
        float l0 = __logf(em0 + 1e-10f) + sG2[h * NP1 + i0];
        float l1 = has1 ? (__logf(em1 + 1e-10f) + sG2[h * NP1 + i1]) : -INFINITY;
        float mx2 = warp_max(fmaxf(l0, l1));
        float t0 = __expf(l0 - mx2), t1 = has1 ? __expf(l1 - mx2) : 0.f;
        float inv2 = 1.0f / warp_sum(t0 + t1);
        out[TOTALE + base + i0] = t0 * inv2;
        if (has1) out[TOTALE + base + i1] = t1 * inv2;
    }
}

// ---------------- launch ----------------
extern "C" void kernel_launch(void* const* d_in, const int* in_sizes, int n_in,
                              void* d_out, int out_size) {
    const float* x       = (const float*)d_in[0];
    const float* A       = (const float*)d_in[1];
    const float* amask   = (const float*)d_in[2];
    const float* W_embed = (const float*)d_in[3];
    const float* b_embed = (const float*)d_in[4];
    const float* ln_g    = (const float*)d_in[5];
    const float* ln_b    = (const float*)d_in[6];
    const float* W_qkv   = (const float*)d_in[7];
    const float* b_qkv   = (const float*)d_in[8];
    const float* W1      = (const float*)d_in[9];
    const float* b1      = (const float*)d_in[10];
    const float* W2      = (const float*)d_in[11];
    const float* b2      = (const float*)d_in[12];
    float* out = (float*)d_out;

    cudaFuncSetAttribute(k3_attn, cudaFuncAttributeMaxDynamicSharedMemorySize, SMEM3_BYTES);

    k0_fold<<<384, 128>>>(W_qkv, b_qkv, W1, b1, ln_g, ln_b, W_embed);
    k1_pq<<<BSZ * NP1, 128>>>(x, amask, W_embed, b_embed);
    kP_gemm<<<(12416 + 55) / 56, 256>>>();
    k3_attn<<<BSZ * NN, NT, SMEM3_BYTES>>>(A, amask, W_embed, W2, b2, out);
}

// round 16
// speedup vs baseline: 1.4864x; 1.4864x over previous
#include <cuda_runtime.h>
#include <cstdint>

#define BSZ 128
#define NN 48
#define NP1 49
#define DM 32
#define DMODEL 128
#define NHEAD 4
#define HD 32
#define TOTALE (BSZ*NN*NHEAD*NP1)

typedef unsigned long long ull;

// ---------------- device scratch ----------------
__device__ float g_P[BSZ * NP1 * DMODEL];
__device__ float g_Q[BSZ * NN * DMODEL];
__device__ float g_Wg[DMODEL * 384];
__device__ float g_M2[DM * 384];
__device__ float g_S[384];
__device__ float g_C[384];
__device__ float g_PQ2[(size_t)12416 * 384];

// ---------------- helpers ----------------
__device__ __forceinline__ float warp_sum(float v) {
    #pragma unroll
    for (int o = 16; o > 0; o >>= 1) v += __shfl_xor_sync(0xffffffffu, v, o);
    return v;
}
__device__ __forceinline__ float warp_max(float v) {
    #pragma unroll
    for (int o = 16; o > 0; o >>= 1) v = fmaxf(v, __shfl_xor_sync(0xffffffffu, v, o));
    return v;
}
__device__ __forceinline__ unsigned rotl32(unsigned v, int r) { return (v << r) | (v >> (32 - r)); }
__device__ __forceinline__ ull fma2(ull a, ull b, ull c) {
    ull d; asm("fma.rn.f32x2 %0, %1, %2, %3;" : "=l"(d) : "l"(a), "l"(b), "l"(c)); return d;
}
__device__ __forceinline__ ull add2(ull a, ull b) {
    ull d; asm("add.rn.f32x2 %0, %1, %2;" : "=l"(d) : "l"(a), "l"(b)); return d;
}
__device__ __forceinline__ ull pack2(float lo, float hi) {
    ull d; asm("mov.b64 %0, {%1, %2};" : "=l"(d) : "f"(lo), "f"(hi)); return d;
}
__device__ __forceinline__ ull dup2(float v) {
    ull d; asm("mov.b64 %0, {%1, %1};" : "=l"(d) : "f"(v)); return d;
}
__device__ __forceinline__ void unpack2(ull v, float& lo, float& hi) {
    asm("mov.b64 {%0, %1}, %2;" : "=f"(lo), "=f"(hi) : "l"(v));
}
__device__ float gumbel_noise(unsigned idx) {   // JAX partitionable threefry (verified R2-R12)
    unsigned x0 = 0u, x1 = idx;
    const unsigned ks0 = 0u, ks1 = 42u, ks2 = 0x1BD11BDAu ^ 0u ^ 42u;
    x0 += ks0; x1 += ks1;
#define TFR(r) { x0 += x1; x1 = rotl32(x1, r); x1 ^= x0; }
    TFR(13) TFR(15) TFR(26) TFR(6)   x0 += ks1; x1 += ks2 + 1u;
    TFR(17) TFR(29) TFR(16) TFR(24)  x0 += ks2; x1 += ks0 + 2u;
    TFR(13) TFR(15) TFR(26) TFR(6)   x0 += ks0; x1 += ks1 + 3u;
    TFR(17) TFR(29) TFR(16) TFR(24)  x0 += ks1; x1 += ks2 + 4u;
    TFR(13) TFR(15) TFR(26) TFR(6)   x0 += ks2; x1 += ks0 + 5u;
#undef TFR
    unsigned bits = x0 ^ x1;
    float u = __uint_as_float((bits >> 9) | 0x3f800000u) - 1.0f;
    return -logf(-log1pf(-u));
}

// ---------------- k0: build Wg, S, C, M2 (unchanged) ----------------
__global__ void k0_fold(const float* __restrict__ W_qkv, const float* __restrict__ b_qkv,
                        const float* __restrict__ W1, const float* __restrict__ b1,
                        const float* __restrict__ ln_g, const float* __restrict__ ln_b,
                        const float* __restrict__ W_embed) {
    int n = blockIdx.x, d = threadIdx.x;
    const float scale = 0.1767766952966369f;
    int h = (n - 256) >> 5, dp = (n - 256) & 31;
    float wf;
    if (n < 128) wf = W_qkv[d * 384 + n] * scale;
    else if (n < 256) wf = W_qkv[d * 384 + n];
    else {
        float acc = 0.f;
        #pragma unroll 8
        for (int c = 0; c < 32; c++)
            acc = fmaf(W_qkv[d * 384 + 256 + 32 * h + c], W1[c * 32 + dp], acc);
        wf = acc;
    }
    float wg = ln_g[d] * wf;
    g_Wg[d * 384 + n] = wg;
    __shared__ float sw[128], red[128];
    sw[d] = wg;
    red[d] = wg;
    __syncthreads();
    for (int s = 64; s > 0; s >>= 1) { if (d < s) red[d] += red[d + s]; __syncthreads(); }
    float Sv = red[0];
    __syncthreads();
    red[d] = ln_b[d] * wf;
    __syncthreads();
    for (int s = 64; s > 0; s >>= 1) { if (d < s) red[d] += red[d + s]; __syncthreads(); }
    if (d == 0) {
        float bias;
        if (n < 128) bias = b_qkv[n] * scale;
        else if (n < 256) bias = b_qkv[n];
        else {
            bias = b1[dp];
            #pragma unroll 8
            for (int c = 0; c < 32; c++)
                bias = fmaf(b_qkv[256 + 32 * h + c], W1[c * 32 + dp], bias);
        }
        g_S[n] = Sv;
        g_C[n] = red[0] + bias;
    }
    if (d < 32) {
        float acc = 0.f;
        #pragma unroll 16
        for (int dd = 0; dd < 128; dd++)
            acc = fmaf(W_embed[(64 + d) * 128 + dd], sw[dd], acc);
        g_M2[d * 384 + n] = acc;
    }
}

// ---------------- k1: P, Q (unchanged) ----------------
__global__ void k1_pq(const float* __restrict__ x, const float* __restrict__ attn_mask,
                      const float* __restrict__ W_embed, const float* __restrict__ b_embed) {
    int b = blockIdx.x / NP1, n = blockIdx.x % NP1, d = threadIdx.x;
    if (n == NN) { g_P[((size_t)b * NP1 + NN) * DMODEL + d] = b_embed[d]; return; }
    __shared__ float am[NN];
    __shared__ float xm[DM];
    if (d < NN) am[d] = attn_mask[((size_t)b * NN + n) * NN + d];
    __syncthreads();
    float s = 0.f;
    #pragma unroll
    for (int c = 0; c < NN; c++) s += am[c];
    if (d < DM) xm[d] = x[((size_t)b * NN + n) * DM + d] * ((s > 0.f) ? 1.f : 0.f);
    __syncthreads();
    float p = b_embed[d], q = 0.f;
    #pragma unroll
    for (int c = 0; c < DM; c++) {
        float xc = xm[c];
        p = fmaf(xc, W_embed[c * DMODEL + d], p);
        q = fmaf(xc, W_embed[(DM + c) * DMODEL + d], q);
    }
    g_P[((size_t)b * NP1 + n) * DMODEL + d] = p;
    g_Q[((size_t)b * NN + n) * DMODEL + d] = q;
}

// ---------------- kP v2: PQ2 = [P;Q] @ Wg — 32 rows/block, full-lane e loads ----------------
__global__ void __launch_bounds__(256) kP_gemm() {
    __shared__ float wt[32 * 384];   // 48 KB
    int tid = threadIdx.x, lane = tid & 31, w = tid >> 5;
    int base = blockIdx.x * 32;
    ull acc2[4][6];
    #pragma unroll
    for (int rr = 0; rr < 4; rr++)
        #pragma unroll
        for (int k = 0; k < 6; k++) acc2[rr][k] = 0ull;
    for (int d0 = 0; d0 < DMODEL; d0 += 32) {
        for (int t = tid; t < 32 * 384 / 4; t += 256)
            ((float4*)wt)[t] = ((const float4*)(g_Wg + (size_t)d0 * 384))[t];
        __syncthreads();
        float eReg[4];
        #pragma unroll
        for (int rr = 0; rr < 4; rr++) {
            int gr = base + w + 8 * rr;
            float v = 0.f;
            if (gr < 12416) {
                v = (gr < 6272) ? g_P[(size_t)gr * DMODEL + d0 + lane]
                                : g_Q[(size_t)(gr - 6272) * DMODEL + d0 + lane];
            }
            eReg[rr] = v;
        }
        #pragma unroll 4
        for (int dd = 0; dd < 32; dd++) {
            ulonglong2 wv0 = ((const ulonglong2*)(wt + dd * 384))[lane];
            ulonglong2 wv1 = ((const ulonglong2*)(wt + dd * 384 + 128))[lane];
            ulonglong2 wv2 = ((const ulonglong2*)(wt + dd * 384 + 256))[lane];
            #pragma unroll
            for (int rr = 0; rr < 4; rr++) {
                ull e2 = dup2(__shfl_sync(0xffffffffu, eReg[rr], dd));
                acc2[rr][0] = fma2(e2, wv0.x, acc2[rr][0]);
                acc2[rr][1] = fma2(e2, wv0.y, acc2[rr][1]);
                acc2[rr][2] = fma2(e2, wv1.x, acc2[rr][2]);
                acc2[rr][3] = fma2(e2, wv1.y, acc2[rr][3]);
                acc2[rr][4] = fma2(e2, wv2.x, acc2[rr][4]);
                acc2[rr][5] = fma2(e2, wv2.y, acc2[rr][5]);
            }
        }
        __syncthreads();
    }
    #pragma unroll
    for (int rr = 0; rr < 4; rr++) {
        int gr = base + w + 8 * rr;
        if (gr < 12416) {
            #pragma unroll
            for (int k4 = 0; k4 < 3; k4++) {
                float v0, v1, v2, v3;
                unpack2(acc2[rr][2*k4], v0, v1);
                unpack2(acc2[rr][2*k4+1], v2, v3);
                *(float4*)(g_PQ2 + (size_t)gr * 384 + 128 * k4 + 4 * lane) = make_float4(v0, v1, v2, v3);
            }
        }
    }
}

// ---------------- k3 (R12 verbatim) smem layout (floats) ----------------
#define OFF_AE  0        /* 56*32 = 1792, persists */
#define OFF_BIG 1920
#define QSTR    132
#define OFF_Q   1920     /* 49*132=6468 ->8388 */
#define OFF_V   8388     /* ->14856 */
#define KTSTR   52
#define OFF_KT  14856    /* 128*52=6656 ->21512 */
#define OFF_M   21512    /* 64 */
#define OFF_S   21576    /* 384 */
#define OFF_C   21960    /* 384 */
#define OFF_W2  22344    /* 32 */
#define OFF_G   22376    /* 200 -> 22576 */
#define OFF_G2  22576    /* 196 -> 22772 */
#define SMEM3_FLOATS 22772
#define SMEM3_BYTES (SMEM3_FLOATS * 4)

__global__ void __launch_bounds__(256, 2) k3_attn(
    const float* __restrict__ A, const float* __restrict__ attn_mask,
    const float* __restrict__ W_embed, const float* __restrict__ W2,
    const float* __restrict__ b2, float* __restrict__ out) {
    extern __shared__ float sm[];
    int bj = blockIdx.x, b = bj / NN, j = bj % NN;
    int tid = threadIdx.x, lane = tid & 31, w = tid >> 5;
    bool wzero = (w == 0);
    float* sAE = sm + OFF_AE;
    float* sWA = sm + OFF_BIG;
    float* sM2 = sm + OFF_BIG;
    float* sQ  = sm + OFF_Q;
    float* sV  = sm + OFF_V;
    float* sKT = sm + OFF_KT;
    float* sM  = sm + OFF_M;
    float* sS  = sm + OFF_S;
    float* sC  = sm + OFF_C;
    float* sW2 = sm + OFF_W2;
    float* sG  = sm + OFF_G;
    float* sG2 = sm + OFF_G2;

    // ---- init loads (+ precompute gumbel noise) ----
    if (tid < 64) sM[tid] = (tid < NN) ? attn_mask[((size_t)b * NN + j) * NN + tid]
                                       : (tid == NN ? 1.0f : 0.0f);
    for (int t = tid; t < 384; t += 256) { sS[t] = g_S[t]; sC[t] = g_C[t]; }
    if (tid < 32) sW2[tid] = W2[tid];
    for (int t = tid; t < DM * DMODEL; t += 256) sWA[t] = W_embed[(2 * DM) * DMODEL + t];
    for (int t = tid; t < 128 * 3; t += 256) sKT[(t / 3) * KTSTR + 49 + (t % 3)] = 0.f;
    if (tid < 196) sG2[tid] = gumbel_noise((unsigned)bj * 196u + (unsigned)tid);
    __syncthreads();

    // ---- stage masked A rows ----
    #pragma unroll
    for (int rr = 0; rr < 7; rr++) {
        int row = w + 8 * rr;
        if (rr < 6 || wzero) {
            float a = 0.f;
            if (row < NN) a = A[(((size_t)b * NN + row) * NN + j) * DM + lane] * sM[row];
            sAE[(w * 7 + rr) * DM + lane] = a;
        }
    }
    __syncwarp();

    // ---- LN stats: raw = P + Q + a@WA ----
    float rsR[7], msR[7];
    {
        const float2* Pb2 = (const float2*)(g_P + (size_t)b * NP1 * DMODEL);
        const float2* Qb2 = (const float2*)(g_Q + ((size_t)b * NN + j) * DMODEL);
        const ull* wt2 = (const ull*)sWA;
        float2 qva = Qb2[lane], qvb = Qb2[32 + lane];
        ull e0[7], e1[7];
        #pragma unroll
        for (int rr = 0; rr < 7; rr++) {
            int row = w + 8 * rr;
            if (rr < 6 || wzero) {
                float2 p0 = Pb2[row * 64 + lane], p1 = Pb2[row * 64 + 32 + lane];
                e0[rr] = pack2(p0.x + qva.x, p0.y + qva.y);
                e1[rr] = pack2(p1.x + qvb.x, p1.y + qvb.y);
            }
        }
        #pragma unroll 2
        for (int cg = 0; cg < 8; cg++) {
            float4 a4[7];
            #pragma unroll
            for (int rr = 0; rr < 7; rr++)
                if (rr < 6 || wzero) a4[rr] = *(const float4*)(sAE + (w * 7 + rr) * DM + 4 * cg);
            #pragma unroll
            for (int t = 0; t < 4; t++) {
                int c = 4 * cg + t;
                ull wv0 = wt2[c * 64 + lane], wv1 = wt2[c * 64 + 32 + lane];
                #pragma unroll
                for (int rr = 0; rr < 7; rr++) {
                    if (rr < 6 || wzero) {
                        ull ac = dup2(((const float*)&a4[rr])[t]);
                        e0[rr] = fma2(ac, wv0, e0[rr]);
                        e1[rr] = fma2(ac, wv1, e1[rr]);
                    }
                }
            }
        }
        #pragma unroll
        for (int rr = 0; rr < 7; rr++) {
            if (rr < 6 || wzero) {
                float v0, v1, v2, v3;
                unpack2(e0[rr], v0, v1); unpack2(e1[rr], v2, v3);
                float mu = warp_sum(v0 + v1 + v2 + v3) * (1.0f / DMODEL);
                float d0 = v0 - mu, d1 = v1 - mu, d2 = v2 - mu, d3 = v3 - mu;
                float rs = rsqrtf(warp_sum(d0*d0 + d1*d1 + d2*d2 + d3*d3) * (1.0f / DMODEL) + 1e-5f);
                rsR[rr] = rs;
                msR[rr] = rs * mu;
            }
        }
    }
    __syncthreads();

    // ---- load M2 tile (overwrites sWA region) ----
    for (int t = tid; t < DM * 384 / 4; t += 256)
        ((float4*)sM2)[t] = ((const float4*)g_M2)[t];
    __syncthreads();

    // ---- qkv: acc = P2 + Q2 + a@M2 ----
    ull acc2[7][6];
    {
        const ull* q2p = (const ull*)(g_PQ2 + (size_t)(6272 + b * NN + j) * 384);
        ull q2u[6];
        #pragma unroll
        for (int k4 = 0; k4 < 3; k4++) {
            q2u[2*k4]   = q2p[64 * k4 + 2 * lane];
            q2u[2*k4+1] = q2p[64 * k4 + 2 * lane + 1];
        }
        #pragma unroll
        for (int rr = 0; rr < 7; rr++) {
            int row = w + 8 * rr;
            if (rr < 6 || wzero) {
                const float4* p2r = (const float4*)(g_PQ2 + (size_t)(b * NP1 + row) * 384);
                #pragma unroll
                for (int k4 = 0; k4 < 3; k4++) {
                    float4 p4 = p2r[32 * k4 + lane];
                    acc2[rr][2*k4]   = add2(pack2(p4.x, p4.y), q2u[2*k4]);
                    acc2[rr][2*k4+1] = add2(pack2(p4.z, p4.w), q2u[2*k4+1]);
                }
            }
        }
        #pragma unroll 2
        for (int cg = 0; cg < 8; cg++) {
            float4 a4[7];
            #pragma unroll
            for (int rr = 0; rr < 7; rr++)
                if (rr < 6 || wzero) a4[rr] = *(const float4*)(sAE + (w * 7 + rr) * DM + 4 * cg);
            #pragma unroll
            for (int t = 0; t < 4; t++) {
                int c = 4 * cg + t;
                ulonglong2 wv0 = ((const ulonglong2*)(sM2 + c * 384))[lane];
                ulonglong2 wv1 = ((const ulonglong2*)(sM2 + c * 384 + 128))[lane];
                ulonglong2 wv2 = ((const ulonglong2*)(sM2 + c * 384 + 256))[lane];
                #pragma unroll
                for (int rr = 0; rr < 7; rr++) {
                    if (rr < 6 || wzero) {
                        ull ac = dup2(((const float*)&a4[rr])[t]);
                        acc2[rr][0] = fma2(ac, wv0.x, acc2[rr][0]);
                        acc2[rr][1] = fma2(ac, wv0.y, acc2[rr][1]);
                        acc2[rr][2] = fma2(ac, wv1.x, acc2[rr][2]);
                        acc2[rr][3] = fma2(ac, wv1.y, acc2[rr][3]);
                        acc2[rr][4] = fma2(ac, wv2.x, acc2[rr][4]);
                        acc2[rr][5] = fma2(ac, wv2.y, acc2[rr][5]);
                    }
                }
            }
        }
    }
    __syncthreads();   // all warps done reading sM2 before scatter overwrites it

    // ---- epilogue + scatter q / k^T / v' ----
    const ull* sS2 = (const ull*)sS;
    const ull* sC2 = (const ull*)sC;
    #pragma unroll
    for (int rr = 0; rr < 7; rr++) {
        int row = w + 8 * rr;
        if (rr < 6 || wzero) {
            ull rs2 = dup2(rsR[rr]), nm2 = dup2(-msR[rr]);
            float o[12];
            #pragma unroll
            for (int k4 = 0; k4 < 3; k4++) {
                #pragma unroll
                for (int u = 0; u < 2; u++) {
                    int k = 2 * k4 + u;
                    ull sv = sS2[64 * k4 + 2 * lane + u];
                    ull cv = sC2[64 * k4 + 2 * lane + u];
                    ull res = fma2(rs2, acc2[rr][k], fma2(nm2, sv, cv));
                    unpack2(res, o[4*k4 + 2*u], o[4*k4 + 2*u + 1]);
                }
            }
            *(float4*)(sQ + row * QSTR + 4 * lane) = make_float4(o[0], o[1], o[2], o[3]);
            *(float4*)(sV + row * QSTR + 4 * lane) = make_float4(o[8], o[9], o[10], o[11]);
            int kd = 4 * lane;
            sKT[kd * KTSTR + row] = o[4];
            sKT[(kd + 1) * KTSTR + row] = o[5];
            sKT[(kd + 2) * KTSTR + row] = o[6];
            sKT[(kd + 3) * KTSTR + row] = o[7];
        }
    }
    __syncthreads();

    // ---- attention: blk = (head h, 7 i-rows) ----
    float b2v = b2[0], w2r = sW2[lane];
    float m0 = sM[2 * lane], m1 = sM[2 * lane + 1];
    bool vj0 = (2 * lane) < NP1, vj1 = (2 * lane + 1) < NP1;
    for (int blk = w; blk < 28; blk += 8) {
        int h = blk & 3, ibase = (blk >> 2) * 7;
        ull s2[7];
        #pragma unroll
        for (int r = 0; r < 7; r++) s2[r] = 0ull;
        const float* ktb = sKT + (h * HD) * KTSTR + 2 * lane;
        #pragma unroll 2
        for (int dq = 0; dq < 8; dq++) {
            float4 q4[7];
            #pragma unroll
            for (int r = 0; r < 7; r++)
                q4[r] = *(const float4*)(sQ + (ibase + r) * QSTR + h * HD + 4 * dq);
            #pragma unroll
            for (int t = 0; t < 4; t++) {
                int d = 4 * dq + t;
                ull kv2 = (lane < 26) ? *(const ull*)(ktb + d * KTSTR) : 0ull;
                #pragma unroll
                for (int r = 0; r < 7; r++) {
                    ull qd = dup2(((const float*)&q4[r])[t]);
                    s2[r] = fma2(qd, kv2, s2[r]);
                }
            }
        }
        ull p2[7];
        float invr[7];
        #pragma unroll
        for (int r = 0; r < 7; r++) {
            float mi = sM[ibase + r];
            float s0, s1;
            unpack2(s2[r], s0, s1);
            s0 = vj0 ? ((mi * m0 > 0.f) ? s0 : -1e9f) : -INFINITY;
            s1 = vj1 ? ((mi * m1 > 0.f) ? s1 : -1e9f) : -INFINITY;
            float mx = warp_max(fmaxf(s0, s1));
            float e0 = vj0 ? __expf(s0 - mx) : 0.f;
            float e1 = vj1 ? __expf(s1 - mx) : 0.f;
            invr[r] = 1.0f / warp_sum(e0 + e1);
            p2[r] = pack2(e0, e1);
        }
        ull t2[7];
        #pragma unroll
        for (int r = 0; r < 7; r++) t2[r] = 0ull;
        const float* vb = sV + h * HD + lane;
        #pragma unroll 5
        for (int jp = 0; jp < 25; jp++) {
            ull v2 = pack2(vb[(2 * jp) * QSTR], vb[(2 * jp + 1) * QSTR]);
            #pragma unroll
            for (int r = 0; r < 7; r++) {
                ull pp = __shfl_sync(0xffffffffu, p2[r], jp);
                t2[r] = fma2(pp, v2, t2[r]);
            }
        }
        #pragma unroll
        for (int r = 0; r < 7; r++) {
            float tlo, thi;
            unpack2(t2[r], tlo, thi);
            float t = fmaxf((tlo + thi) * invr[r], 0.f);
            float gp = warp_sum(t * w2r);
            if (lane == 0) sG[h * NP1 + ibase + r] = gp + b2v;
        }
    }
    __syncthreads();

    // ---- em softmax + gumbel (warp = head; noise precomputed in sG2) ----
    if (w < NHEAD) {
        int h = w, i0 = lane, i1 = lane + 32;
        bool has1 = (i1 < NP1);
        float g0 = sG[h * NP1 + i0];
        float g1 = has1 ? sG[h * NP1 + i1] : -INFINITY;
        float mx = warp_max(fmaxf(g0, g1));
        float e0 = __expf(g0 - mx), e1 = has1 ? __expf(g1 - mx) : 0.f;
        float inv = 1.0f / warp_sum(e0 + e1);
        float em0 = e0 * inv * sM[i0];
        float em1 = has1 ? e1 * inv * sM[i1] : 0.f;
        float den = warp_sum(em0 + em1) + 1e-10f;
        em0 /= den; em1 /= den;
        size_t base = (((size_t)b * NN + j) * NHEAD + h) * NP1;
        out[base + i0] = em0;
        if (has1) out[base + i1] = em1;
        float l0 = __logf(em0 + 1e-10f) + sG2[h * NP1 + i0];
        float l1 = has1 ? (__logf(em1 + 1e-10f) + sG2[h * NP1 + i1]) : -INFINITY;
        float mx2 = warp_max(fmaxf(l0, l1));
        float t0 = __expf(l0 - mx2), t1 = has1 ? __expf(l1 - mx2) : 0.f;
        float inv2 = 1.0f / warp_sum(t0 + t1);
        out[TOTALE + base + i0] = t0 * inv2;
        if (has1) out[TOTALE + base + i1] = t1 * inv2;
    }
}

// ---------------- launch ----------------
extern "C" void kernel_launch(void* const* d_in, const int* in_sizes, int n_in,
                              void* d_out, int out_size) {
    const float* x       = (const float*)d_in[0];
    const float* A       = (const float*)d_in[1];
    const float* amask   = (const float*)d_in[2];
    const float* W_embed = (const float*)d_in[3];
    const float* b_embed = (const float*)d_in[4];
    const float* ln_g    = (const float*)d_in[5];
    const float* ln_b    = (const float*)d_in[6];
    const float* W_qkv   = (const float*)d_in[7];
    const float* b_qkv   = (const float*)d_in[8];
    const float* W1      = (const float*)d_in[9];
    const float* b1      = (const float*)d_in[10];
    const float* W2      = (const float*)d_in[11];
    const float* b2      = (const float*)d_in[12];
    float* out = (float*)d_out;

    cudaFuncSetAttribute(k3_attn, cudaFuncAttributeMaxDynamicSharedMemorySize, SMEM3_BYTES);

    k0_fold<<<384, 128>>>(W_qkv, b_qkv, W1, b1, ln_g, ln_b, W_embed);
    k1_pq<<<BSZ * NP1, 128>>>(x, amask, W_embed, b_embed);
    kP_gemm<<<(12416 + 31) / 32, 256>>>();
    k3_attn<<<BSZ * NN, 256, SMEM3_BYTES>>>(A, amask, W_embed, W2, b2, out);
}